// round 1
// baseline (speedup 1.0000x reference)
#include <cuda_runtime.h>
#include <cuda_bf16.h>
#include <math.h>

// ---------------------------------------------------------------------------
// Problem constants (fixed by the dataset)
// ---------------------------------------------------------------------------
#define NN   50000      // nodes
#define EE   400000     // edges (without self loops)
#define ETOT (EE + NN)  // edges + self loops
#define GG   256        // graphs
#define FMAX 256        // max feature width (H1*EMB)

// ---------------------------------------------------------------------------
// Scratch (static device allocations -- no runtime allocs allowed)
// ---------------------------------------------------------------------------
__device__ float    g_xl[(size_t)NN * FMAX];
__device__ float    g_xr[(size_t)NN * FMAX];
__device__ float    g_h [(size_t)NN * FMAX];
__device__ int      g_deg [NN];
__device__ int      g_row [NN + 1];
__device__ int      g_fill[NN];
__device__ int      g_col [ETOT];
__device__ unsigned g_gmax[GG * 64];
__device__ float    g_gsum[GG * 64];
__device__ int      g_cnt [GG];

// ---------------------------------------------------------------------------
// Helpers: order-preserving float<->uint for atomicMax on floats
// ---------------------------------------------------------------------------
__device__ __forceinline__ unsigned fkey(float f) {
    unsigned u = __float_as_uint(f);
    return (u & 0x80000000u) ? ~u : (u | 0x80000000u);
}
__device__ __forceinline__ float fdec(unsigned u) {
    unsigned b = (u & 0x80000000u) ? (u ^ 0x80000000u) : ~u;
    return __uint_as_float(b);
}
// fkey(-inf) = ~0xFF800000 = 0x007FFFFF
#define FKEY_NEG_INF 0x007FFFFFu

// ---------------------------------------------------------------------------
// Init: zero degree counters + pooling accumulators
// ---------------------------------------------------------------------------
__global__ void init_kernel(int* deg, unsigned* gmax, float* gsum, int* cnt) {
    int i = blockIdx.x * blockDim.x + threadIdx.x;
    if (i < NN) deg[i] = 0;
    if (i < GG * 64) { gmax[i] = FKEY_NEG_INF; gsum[i] = 0.0f; }
    if (i < GG) cnt[i] = 0;
}

// ---------------------------------------------------------------------------
// CSR build: histogram over destination node
// ---------------------------------------------------------------------------
__global__ void hist_kernel(const int* __restrict__ edge_index, int* deg) {
    int e = blockIdx.x * blockDim.x + threadIdx.x;
    if (e >= ETOT) return;
    int dst = (e < EE) ? edge_index[EE + e] : (e - EE);
    atomicAdd(&deg[dst], 1);
}

// Single-block exclusive/inclusive scan over NN degrees -> row ptr + fill ptr
__global__ void scan_kernel(const int* __restrict__ deg, int* __restrict__ row,
                            int* __restrict__ fill) {
    __shared__ int wsum[32];
    __shared__ int carry_s;
    int tid = threadIdx.x, lane = tid & 31, wid = tid >> 5;
    if (tid == 0) carry_s = 0;
    __syncthreads();
    for (int base = 0; base < NN; base += 1024) {
        int i = base + tid;
        int v = (i < NN) ? deg[i] : 0;
        int x = v;
        #pragma unroll
        for (int o = 1; o < 32; o <<= 1) {
            int t = __shfl_up_sync(0xffffffffu, x, o);
            if (lane >= o) x += t;
        }
        if (lane == 31) wsum[wid] = x;
        __syncthreads();
        if (wid == 0) {
            int s = wsum[lane];
            #pragma unroll
            for (int o = 1; o < 32; o <<= 1) {
                int t = __shfl_up_sync(0xffffffffu, s, o);
                if (lane >= o) s += t;
            }
            wsum[lane] = s;
        }
        __syncthreads();
        int offset = carry_s + (wid > 0 ? wsum[wid - 1] : 0);
        int incl = offset + x;
        if (i < NN) { row[i + 1] = incl; fill[i] = incl - v; }
        if (i == 0) row[0] = 0;
        __syncthreads();
        if (tid == 1023) carry_s += wsum[31];
        __syncthreads();
    }
}

__global__ void scatter_kernel(const int* __restrict__ edge_index,
                               int* fill, int* __restrict__ col) {
    int e = blockIdx.x * blockDim.x + threadIdx.x;
    if (e >= ETOT) return;
    int src, dst;
    if (e < EE) { src = edge_index[e]; dst = edge_index[EE + e]; }
    else        { src = e - EE;        dst = e - EE; }
    int pos = atomicAdd(&fill[dst], 1);
    col[pos] = src;
}

// ---------------------------------------------------------------------------
// SGEMM: C[N,M] = A[N,K] * W[M,K]^T   (both K-contiguous, fp32)
// 128x128 tile, BK=8, 256 threads, 8x8 micro-tile
// ---------------------------------------------------------------------------
__global__ __launch_bounds__(256) void sgemm_nt(const float* __restrict__ A,
                                                const float* __restrict__ W,
                                                float* __restrict__ C,
                                                int Nrows, int K, int M) {
    __shared__ float As[8][128];
    __shared__ float Bs[8][128];
    int tid = threadIdx.x;
    int tx = tid % 16, ty = tid / 16;
    int rowBase = blockIdx.y * 128;
    int colBase = blockIdx.x * 128;
    int lr = tid >> 1;            // 0..127: tile row loaded by this thread
    int lk = (tid & 1) * 4;       // 0 or 4: K sub-offset (float4)

    float acc[8][8];
    #pragma unroll
    for (int i = 0; i < 8; i++)
        #pragma unroll
        for (int j = 0; j < 8; j++) acc[i][j] = 0.0f;

    for (int k0 = 0; k0 < K; k0 += 8) {
        float4 a4 = make_float4(0.f, 0.f, 0.f, 0.f);
        int ar = rowBase + lr;
        if (ar < Nrows) a4 = *(const float4*)&A[(size_t)ar * K + k0 + lk];
        As[lk + 0][lr] = a4.x; As[lk + 1][lr] = a4.y;
        As[lk + 2][lr] = a4.z; As[lk + 3][lr] = a4.w;

        float4 b4 = make_float4(0.f, 0.f, 0.f, 0.f);
        int br = colBase + lr;
        if (br < M) b4 = *(const float4*)&W[(size_t)br * K + k0 + lk];
        Bs[lk + 0][lr] = b4.x; Bs[lk + 1][lr] = b4.y;
        Bs[lk + 2][lr] = b4.z; Bs[lk + 3][lr] = b4.w;
        __syncthreads();

        #pragma unroll
        for (int k = 0; k < 8; k++) {
            float a[8], b[8];
            #pragma unroll
            for (int i = 0; i < 8; i++) a[i] = As[k][ty * 8 + i];
            #pragma unroll
            for (int j = 0; j < 8; j++) b[j] = Bs[k][tx * 8 + j];
            #pragma unroll
            for (int i = 0; i < 8; i++)
                #pragma unroll
                for (int j = 0; j < 8; j++) acc[i][j] = fmaf(a[i], b[j], acc[i][j]);
        }
        __syncthreads();
    }

    #pragma unroll
    for (int i = 0; i < 8; i++) {
        int r = rowBase + ty * 8 + i;
        if (r >= Nrows) continue;
        #pragma unroll
        for (int j = 0; j < 8; j++) {
            int c = colBase + tx * 8 + j;
            if (c < M) C[(size_t)r * M + c] = acc[i][j];
        }
    }
}

// ---------------------------------------------------------------------------
// GATv2 aggregation: one warp per destination node, online softmax.
//   e_j = att . leaky_relu_0.2(xl[src_j] + xr[dst])
//   out  = leaky_relu_0.01( (sum_j exp(e_j - m) xl[src_j]) / (sum_j exp(e_j-m) + 1e-16) + bias )
// head(feature f) = f/64 ; with f = lane + 32k this is k>>1 for all H in {1,2,4}.
// ---------------------------------------------------------------------------
template <int H>
__global__ __launch_bounds__(256) void gat_agg_kernel(
    const float* __restrict__ xl, const float* __restrict__ xr,
    const int* __restrict__ rowptr, const int* __restrict__ colidx,
    const float* __restrict__ att, const float* __restrict__ bias,
    float* __restrict__ out) {
    constexpr int F = H * 64;
    constexpr int FPL = F / 32;
    int warp = (blockIdx.x * blockDim.x + threadIdx.x) >> 5;
    int lane = threadIdx.x & 31;
    if (warp >= NN) return;

    float xr_r[FPL], att_r[FPL];
    #pragma unroll
    for (int k = 0; k < FPL; k++) {
        int f = lane + 32 * k;
        xr_r[k] = xr[(size_t)warp * F + f];
        att_r[k] = att[f];
    }

    float emax[H], psum[H], acc[FPL];
    #pragma unroll
    for (int h = 0; h < H; h++) { emax[h] = -INFINITY; psum[h] = 0.0f; }
    #pragma unroll
    for (int k = 0; k < FPL; k++) acc[k] = 0.0f;

    int beg = rowptr[warp], end = rowptr[warp + 1];
    for (int j = beg; j < end; j++) {
        int s = colidx[j];
        float xlv[FPL];
        float part[H];
        #pragma unroll
        for (int h = 0; h < H; h++) part[h] = 0.0f;
        #pragma unroll
        for (int k = 0; k < FPL; k++) {
            float v = __ldg(&xl[(size_t)s * F + lane + 32 * k]);
            xlv[k] = v;
            float z = v + xr_r[k];
            z = z > 0.0f ? z : 0.2f * z;
            part[k >> 1] += att_r[k] * z;
        }
        #pragma unroll
        for (int h = 0; h < H; h++) {
            #pragma unroll
            for (int o = 16; o > 0; o >>= 1)
                part[h] += __shfl_xor_sync(0xffffffffu, part[h], o);
        }
        float pfac[H], corr[H];
        #pragma unroll
        for (int h = 0; h < H; h++) {
            float e = part[h];
            float m = fmaxf(emax[h], e);
            float c = __expf(emax[h] - m);
            float p = __expf(e - m);
            psum[h] = psum[h] * c + p;
            emax[h] = m;
            corr[h] = c; pfac[h] = p;
        }
        #pragma unroll
        for (int k = 0; k < FPL; k++)
            acc[k] = acc[k] * corr[k >> 1] + pfac[k >> 1] * xlv[k];
    }

    #pragma unroll
    for (int k = 0; k < FPL; k++) {
        int f = lane + 32 * k;
        float v = acc[k] / (psum[k >> 1] + 1e-16f) + bias[f];
        v = v > 0.0f ? v : 0.01f * v;   // inter-layer leaky_relu (also applied after layer 3)
        out[(size_t)warp * F + f] = v;
    }
}

// ---------------------------------------------------------------------------
// Pooling: per-(node,feature) atomics into per-graph max / sum; count per node
// ---------------------------------------------------------------------------
__global__ void pool_kernel(const float* __restrict__ h,
                            const int* __restrict__ batch,
                            unsigned* gmax, float* gsum, int* cnt) {
    int idx = blockIdx.x * blockDim.x + threadIdx.x;
    if (idx >= NN * 64) return;
    int n = idx >> 6, f = idx & 63;
    int g = batch[n];
    float v = h[idx];
    atomicMax(&gmax[g * 64 + f], fkey(v));
    atomicAdd(&gsum[g * 64 + f], v);
    if (f == 0) atomicAdd(&cnt[g], 1);
}

// ---------------------------------------------------------------------------
// Head: hidden = [gmax | gmean], out = hidden @ out_w^T + out_b
// d_out layout: [0:512) out[256,2], [512:33280) hidden[256,128]
// ---------------------------------------------------------------------------
__global__ void head_kernel(const unsigned* __restrict__ gmax,
                            const float* __restrict__ gsum,
                            const int* __restrict__ cnt,
                            const float* __restrict__ out_w,
                            const float* __restrict__ out_b,
                            float* __restrict__ d_out) {
    int g = blockIdx.x * blockDim.x + threadIdx.x;
    if (g >= GG) return;
    float hid[128];
    int c = cnt[g];
    float inv = 1.0f / (float)(c > 1 ? c : 1);
    for (int f = 0; f < 64; f++) {
        hid[f] = fdec(gmax[g * 64 + f]);
        hid[64 + f] = gsum[g * 64 + f] * inv;
    }
    float* hidden_out = d_out + 512 + (size_t)g * 128;
    for (int f = 0; f < 128; f++) hidden_out[f] = hid[f];
    for (int o = 0; o < 2; o++) {
        float s = out_b[o];
        for (int k = 0; k < 128; k++) s = fmaf(hid[k], out_w[o * 128 + k], s);
        d_out[g * 2 + o] = s;
    }
}

// ---------------------------------------------------------------------------
// Launch
// ---------------------------------------------------------------------------
extern "C" void kernel_launch(void* const* d_in, const int* in_sizes, int n_in,
                              void* d_out, int out_size) {
    const float* x         = (const float*)d_in[0];
    const int*   edge_idx  = (const int*)d_in[1];
    const int*   batch     = (const int*)d_in[2];
    const float* w1_l = (const float*)d_in[3];
    const float* w1_r = (const float*)d_in[4];
    const float* att1 = (const float*)d_in[5];
    const float* b1   = (const float*)d_in[6];
    const float* w2_l = (const float*)d_in[7];
    const float* w2_r = (const float*)d_in[8];
    const float* att2 = (const float*)d_in[9];
    const float* b2   = (const float*)d_in[10];
    const float* w3_l = (const float*)d_in[11];
    const float* w3_r = (const float*)d_in[12];
    const float* att3 = (const float*)d_in[13];
    const float* b3   = (const float*)d_in[14];
    const float* out_w = (const float*)d_in[15];
    const float* out_b = (const float*)d_in[16];
    float* out = (float*)d_out;

    void* p;
    float *xl, *xr, *h, *gsum; int *deg, *row, *fill, *col, *cnt; unsigned* gmax;
    cudaGetSymbolAddress(&p, g_xl);   xl   = (float*)p;
    cudaGetSymbolAddress(&p, g_xr);   xr   = (float*)p;
    cudaGetSymbolAddress(&p, g_h);    h    = (float*)p;
    cudaGetSymbolAddress(&p, g_deg);  deg  = (int*)p;
    cudaGetSymbolAddress(&p, g_row);  row  = (int*)p;
    cudaGetSymbolAddress(&p, g_fill); fill = (int*)p;
    cudaGetSymbolAddress(&p, g_col);  col  = (int*)p;
    cudaGetSymbolAddress(&p, g_gmax); gmax = (unsigned*)p;
    cudaGetSymbolAddress(&p, g_gsum); gsum = (float*)p;
    cudaGetSymbolAddress(&p, g_cnt);  cnt  = (int*)p;

    // --- CSR build (captured each replay; edges are an input) ---
    init_kernel<<<(NN + 255) / 256, 256>>>(deg, gmax, gsum, cnt);
    hist_kernel<<<(ETOT + 255) / 256, 256>>>(edge_idx, deg);
    scan_kernel<<<1, 1024>>>(deg, row, fill);
    scatter_kernel<<<(ETOT + 255) / 256, 256>>>(edge_idx, fill, col);

    const int AGG_BLOCKS = (NN * 32) / 256;  // one warp per node

    // --- Layer 1: F_in=128 -> 4 heads x 64 = 256 ---
    {
        dim3 g1((256 + 127) / 128, (NN + 127) / 128);
        sgemm_nt<<<g1, 256>>>(x, w1_l, xl, NN, 128, 256);
        sgemm_nt<<<g1, 256>>>(x, w1_r, xr, NN, 128, 256);
        gat_agg_kernel<4><<<AGG_BLOCKS, 256>>>(xl, xr, row, col, att1, b1, h);
    }
    // --- Layer 2: 256 -> 2 heads x 64 = 128 ---
    {
        dim3 g2((128 + 127) / 128, (NN + 127) / 128);
        sgemm_nt<<<g2, 256>>>(h, w2_l, xl, NN, 256, 128);
        sgemm_nt<<<g2, 256>>>(h, w2_r, xr, NN, 256, 128);
        gat_agg_kernel<2><<<AGG_BLOCKS, 256>>>(xl, xr, row, col, att2, b2, h);
    }
    // --- Layer 3: 128 -> 1 head x 64 = 64 ---
    {
        dim3 g3((64 + 127) / 128, (NN + 127) / 128);
        sgemm_nt<<<g3, 256>>>(h, w3_l, xl, NN, 128, 64);
        sgemm_nt<<<g3, 256>>>(h, w3_r, xr, NN, 128, 64);
        gat_agg_kernel<1><<<AGG_BLOCKS, 256>>>(xl, xr, row, col, att3, b3, h);
    }

    // --- Pooling + head ---
    pool_kernel<<<(NN * 64 + 255) / 256, 256>>>(h, batch, gmax, gsum, cnt);
    head_kernel<<<1, 256>>>(gmax, gsum, cnt, out_w, out_b, out);
}

// round 2
// speedup vs baseline: 1.7682x; 1.7682x over previous
#include <cuda_runtime.h>
#include <cuda_bf16.h>
#include <math.h>

// ---------------------------------------------------------------------------
// Problem constants (fixed by the dataset)
// ---------------------------------------------------------------------------
#define NN   50000      // nodes
#define EE   400000     // edges (without self loops)
#define ETOT (EE + NN)  // edges + self loops
#define GG   256        // graphs
#define FMAX 256        // max feature width (H1*EMB)

// ---------------------------------------------------------------------------
// Scratch (static device allocations -- no runtime allocs allowed)
// ---------------------------------------------------------------------------
__device__ float    g_xl[(size_t)NN * FMAX];
__device__ float    g_xr[(size_t)NN * FMAX];
__device__ float    g_h [(size_t)NN * FMAX];
__device__ int      g_deg [NN];
__device__ int      g_row [NN + 1];
__device__ int      g_fill[NN];
__device__ int      g_col [ETOT];
__device__ unsigned g_gmax[GG * 64];
__device__ float    g_gsum[GG * 64];
__device__ int      g_cnt [GG];

// ---------------------------------------------------------------------------
// Helpers
// ---------------------------------------------------------------------------
__device__ __forceinline__ unsigned fkey(float f) {
    unsigned u = __float_as_uint(f);
    return (u & 0x80000000u) ? ~u : (u | 0x80000000u);
}
__device__ __forceinline__ float fdec(unsigned u) {
    unsigned b = (u & 0x80000000u) ? (u ^ 0x80000000u) : ~u;
    return __uint_as_float(b);
}
#define FKEY_NEG_INF 0x007FFFFFu

__device__ __forceinline__ float to_tf32(float x) {
    float r;
    asm("cvt.rna.tf32.f32 %0, %1;" : "=f"(r) : "f"(x));
    return r;
}

// ---------------------------------------------------------------------------
// Init
// ---------------------------------------------------------------------------
__global__ void init_kernel(int* deg, unsigned* gmax, float* gsum, int* cnt) {
    int i = blockIdx.x * blockDim.x + threadIdx.x;
    if (i < NN) deg[i] = 0;
    if (i < GG * 64) { gmax[i] = FKEY_NEG_INF; gsum[i] = 0.0f; }
    if (i < GG) cnt[i] = 0;
}

// ---------------------------------------------------------------------------
// CSR build
// ---------------------------------------------------------------------------
__global__ void hist_kernel(const int* __restrict__ edge_index, int* deg) {
    int e = blockIdx.x * blockDim.x + threadIdx.x;
    if (e >= ETOT) return;
    int dst = (e < EE) ? edge_index[EE + e] : (e - EE);
    atomicAdd(&deg[dst], 1);
}

__global__ void scan_kernel(const int* __restrict__ deg, int* __restrict__ row,
                            int* __restrict__ fill) {
    __shared__ int wsum[32];
    __shared__ int carry_s;
    int tid = threadIdx.x, lane = tid & 31, wid = tid >> 5;
    if (tid == 0) carry_s = 0;
    __syncthreads();
    for (int base = 0; base < NN; base += 1024) {
        int i = base + tid;
        int v = (i < NN) ? deg[i] : 0;
        int x = v;
        #pragma unroll
        for (int o = 1; o < 32; o <<= 1) {
            int t = __shfl_up_sync(0xffffffffu, x, o);
            if (lane >= o) x += t;
        }
        if (lane == 31) wsum[wid] = x;
        __syncthreads();
        if (wid == 0) {
            int s = wsum[lane];
            #pragma unroll
            for (int o = 1; o < 32; o <<= 1) {
                int t = __shfl_up_sync(0xffffffffu, s, o);
                if (lane >= o) s += t;
            }
            wsum[lane] = s;
        }
        __syncthreads();
        int offset = carry_s + (wid > 0 ? wsum[wid - 1] : 0);
        int incl = offset + x;
        if (i < NN) { row[i + 1] = incl; fill[i] = incl - v; }
        if (i == 0) row[0] = 0;
        __syncthreads();
        if (tid == 1023) carry_s += wsum[31];
        __syncthreads();
    }
}

__global__ void scatter_kernel(const int* __restrict__ edge_index,
                               int* fill, int* __restrict__ col) {
    int e = blockIdx.x * blockDim.x + threadIdx.x;
    if (e >= ETOT) return;
    int src, dst;
    if (e < EE) { src = edge_index[e]; dst = edge_index[EE + e]; }
    else        { src = e - EE;        dst = e - EE; }
    int pos = atomicAdd(&fill[dst], 1);
    col[pos] = src;
}

// ---------------------------------------------------------------------------
// TF32 tensor-core GEMM: C[N,M] = A[N,K] * W[M,K]^T  (row.col mma, fp32 accum)
// Tile: BM=128, BN=64, BK=32. 256 threads = 8 warps (4 along M x 2 along N).
// Warp tile 32x32 = 2 (m16) x 4 (n8) mma tiles. Smem rows padded to 36 floats
// -> fragment LDS bank = (4*quad + tq) % 32: conflict-free.
// ---------------------------------------------------------------------------
__global__ __launch_bounds__(256) void tf32_gemm(const float* __restrict__ A,
                                                 const float* __restrict__ W,
                                                 float* __restrict__ C,
                                                 int Nrows, int K, int M) {
    __shared__ float As[128][36];
    __shared__ float Bs[64][36];

    int tid = threadIdx.x;
    int lane = tid & 31, wid = tid >> 5;
    int warpM = wid & 3, warpN = wid >> 2;
    int quad = lane >> 2, tq = lane & 3;
    int rowBase = blockIdx.y * 128;
    int colBase = blockIdx.x * 64;

    float acc[2][4][4];
    #pragma unroll
    for (int mi = 0; mi < 2; mi++)
        #pragma unroll
        for (int ni = 0; ni < 4; ni++)
            #pragma unroll
            for (int r = 0; r < 4; r++) acc[mi][ni][r] = 0.0f;

    for (int k0 = 0; k0 < K; k0 += 32) {
        // ---- global -> registers (coalesced float4), convert to tf32 ----
        float4 aReg[4];
        #pragma unroll
        for (int i = 0; i < 4; i++) {
            int fourIdx = tid + 256 * i;          // 0..1023
            int r = fourIdx >> 3;                 // 0..127
            int kq = fourIdx & 7;                 // 0..7
            int gr = rowBase + r;
            float4 v = make_float4(0.f, 0.f, 0.f, 0.f);
            if (gr < Nrows) v = *(const float4*)&A[(size_t)gr * K + k0 + kq * 4];
            aReg[i].x = to_tf32(v.x); aReg[i].y = to_tf32(v.y);
            aReg[i].z = to_tf32(v.z); aReg[i].w = to_tf32(v.w);
        }
        float4 bReg[2];
        #pragma unroll
        for (int i = 0; i < 2; i++) {
            int fourIdx = tid + 256 * i;          // 0..511
            int r = fourIdx >> 3;                 // 0..63
            int kq = fourIdx & 7;
            int gbr = colBase + r;                // M is a multiple of 64
            float4 v = *(const float4*)&W[(size_t)gbr * K + k0 + kq * 4];
            bReg[i].x = to_tf32(v.x); bReg[i].y = to_tf32(v.y);
            bReg[i].z = to_tf32(v.z); bReg[i].w = to_tf32(v.w);
        }

        __syncthreads();   // previous stage's compute done
        #pragma unroll
        for (int i = 0; i < 4; i++) {
            int fourIdx = tid + 256 * i;
            int r = fourIdx >> 3;
            int kq = fourIdx & 7;
            *(float4*)&As[r][kq * 4] = aReg[i];
        }
        #pragma unroll
        for (int i = 0; i < 2; i++) {
            int fourIdx = tid + 256 * i;
            int r = fourIdx >> 3;
            int kq = fourIdx & 7;
            *(float4*)&Bs[r][kq * 4] = bReg[i];
        }
        __syncthreads();

        // ---- compute: 4 k-steps of m16n8k8 ----
        #pragma unroll
        for (int ks = 0; ks < 4; ks++) {
            int kk = ks * 8;
            unsigned a[2][4], b[4][2];
            #pragma unroll
            for (int mi = 0; mi < 2; mi++) {
                int r0 = warpM * 32 + mi * 16 + quad;
                a[mi][0] = __float_as_uint(As[r0    ][kk + tq]);
                a[mi][1] = __float_as_uint(As[r0 + 8][kk + tq]);
                a[mi][2] = __float_as_uint(As[r0    ][kk + tq + 4]);
                a[mi][3] = __float_as_uint(As[r0 + 8][kk + tq + 4]);
            }
            #pragma unroll
            for (int ni = 0; ni < 4; ni++) {
                int c0 = warpN * 32 + ni * 8 + quad;
                b[ni][0] = __float_as_uint(Bs[c0][kk + tq]);
                b[ni][1] = __float_as_uint(Bs[c0][kk + tq + 4]);
            }
            #pragma unroll
            for (int mi = 0; mi < 2; mi++)
                #pragma unroll
                for (int ni = 0; ni < 4; ni++) {
                    asm volatile(
                        "mma.sync.aligned.m16n8k8.row.col.f32.tf32.tf32.f32 "
                        "{%0,%1,%2,%3},{%4,%5,%6,%7},{%8,%9},{%0,%1,%2,%3};"
                        : "+f"(acc[mi][ni][0]), "+f"(acc[mi][ni][1]),
                          "+f"(acc[mi][ni][2]), "+f"(acc[mi][ni][3])
                        : "r"(a[mi][0]), "r"(a[mi][1]), "r"(a[mi][2]), "r"(a[mi][3]),
                          "r"(b[ni][0]), "r"(b[ni][1]));
                }
        }
        __syncthreads();   // compute done before next stage's STS
    }

    // ---- epilogue: float2 stores (c0,c1 are adjacent columns) ----
    #pragma unroll
    for (int mi = 0; mi < 2; mi++) {
        #pragma unroll
        for (int half = 0; half < 2; half++) {
            int r = rowBase + warpM * 32 + mi * 16 + quad + half * 8;
            if (r >= Nrows) continue;
            #pragma unroll
            for (int ni = 0; ni < 4; ni++) {
                int c = colBase + warpN * 32 + ni * 8 + 2 * tq;
                float2 v;
                v.x = acc[mi][ni][half * 2 + 0];
                v.y = acc[mi][ni][half * 2 + 1];
                *(float2*)&C[(size_t)r * M + c] = v;
            }
        }
    }
}

// ---------------------------------------------------------------------------
// GATv2 aggregation: one warp per destination node, online softmax.
// ---------------------------------------------------------------------------
template <int H>
__global__ __launch_bounds__(256) void gat_agg_kernel(
    const float* __restrict__ xl, const float* __restrict__ xr,
    const int* __restrict__ rowptr, const int* __restrict__ colidx,
    const float* __restrict__ att, const float* __restrict__ bias,
    float* __restrict__ out) {
    constexpr int F = H * 64;
    constexpr int FPL = F / 32;
    int warp = (blockIdx.x * blockDim.x + threadIdx.x) >> 5;
    int lane = threadIdx.x & 31;
    if (warp >= NN) return;

    float xr_r[FPL], att_r[FPL];
    #pragma unroll
    for (int k = 0; k < FPL; k++) {
        int f = lane + 32 * k;
        xr_r[k] = xr[(size_t)warp * F + f];
        att_r[k] = att[f];
    }

    float emax[H], psum[H], acc[FPL];
    #pragma unroll
    for (int h = 0; h < H; h++) { emax[h] = -INFINITY; psum[h] = 0.0f; }
    #pragma unroll
    for (int k = 0; k < FPL; k++) acc[k] = 0.0f;

    int beg = rowptr[warp], end = rowptr[warp + 1];
    for (int j = beg; j < end; j++) {
        int s = colidx[j];
        float xlv[FPL];
        float part[H];
        #pragma unroll
        for (int h = 0; h < H; h++) part[h] = 0.0f;
        #pragma unroll
        for (int k = 0; k < FPL; k++) {
            float v = __ldg(&xl[(size_t)s * F + lane + 32 * k]);
            xlv[k] = v;
            float z = v + xr_r[k];
            z = z > 0.0f ? z : 0.2f * z;
            part[k >> 1] += att_r[k] * z;
        }
        #pragma unroll
        for (int h = 0; h < H; h++) {
            #pragma unroll
            for (int o = 16; o > 0; o >>= 1)
                part[h] += __shfl_xor_sync(0xffffffffu, part[h], o);
        }
        float pfac[H], corr[H];
        #pragma unroll
        for (int h = 0; h < H; h++) {
            float e = part[h];
            float m = fmaxf(emax[h], e);
            float c = __expf(emax[h] - m);
            float p = __expf(e - m);
            psum[h] = psum[h] * c + p;
            emax[h] = m;
            corr[h] = c; pfac[h] = p;
        }
        #pragma unroll
        for (int k = 0; k < FPL; k++)
            acc[k] = acc[k] * corr[k >> 1] + pfac[k >> 1] * xlv[k];
    }

    #pragma unroll
    for (int k = 0; k < FPL; k++) {
        int f = lane + 32 * k;
        float v = acc[k] / (psum[k >> 1] + 1e-16f) + bias[f];
        v = v > 0.0f ? v : 0.01f * v;
        out[(size_t)warp * F + f] = v;
    }
}

// ---------------------------------------------------------------------------
// Pooling
// ---------------------------------------------------------------------------
__global__ void pool_kernel(const float* __restrict__ h,
                            const int* __restrict__ batch,
                            unsigned* gmax, float* gsum, int* cnt) {
    int idx = blockIdx.x * blockDim.x + threadIdx.x;
    if (idx >= NN * 64) return;
    int n = idx >> 6, f = idx & 63;
    int g = batch[n];
    float v = h[idx];
    atomicMax(&gmax[g * 64 + f], fkey(v));
    atomicAdd(&gsum[g * 64 + f], v);
    if (f == 0) atomicAdd(&cnt[g], 1);
}

// ---------------------------------------------------------------------------
// Head
// ---------------------------------------------------------------------------
__global__ void head_kernel(const unsigned* __restrict__ gmax,
                            const float* __restrict__ gsum,
                            const int* __restrict__ cnt,
                            const float* __restrict__ out_w,
                            const float* __restrict__ out_b,
                            float* __restrict__ d_out) {
    int g = blockIdx.x * blockDim.x + threadIdx.x;
    if (g >= GG) return;
    float hid[128];
    int c = cnt[g];
    float inv = 1.0f / (float)(c > 1 ? c : 1);
    for (int f = 0; f < 64; f++) {
        hid[f] = fdec(gmax[g * 64 + f]);
        hid[64 + f] = gsum[g * 64 + f] * inv;
    }
    float* hidden_out = d_out + 512 + (size_t)g * 128;
    for (int f = 0; f < 128; f++) hidden_out[f] = hid[f];
    for (int o = 0; o < 2; o++) {
        float s = out_b[o];
        for (int k = 0; k < 128; k++) s = fmaf(hid[k], out_w[o * 128 + k], s);
        d_out[g * 2 + o] = s;
    }
}

// ---------------------------------------------------------------------------
// Launch
// ---------------------------------------------------------------------------
extern "C" void kernel_launch(void* const* d_in, const int* in_sizes, int n_in,
                              void* d_out, int out_size) {
    const float* x         = (const float*)d_in[0];
    const int*   edge_idx  = (const int*)d_in[1];
    const int*   batch     = (const int*)d_in[2];
    const float* w1_l = (const float*)d_in[3];
    const float* w1_r = (const float*)d_in[4];
    const float* att1 = (const float*)d_in[5];
    const float* b1   = (const float*)d_in[6];
    const float* w2_l = (const float*)d_in[7];
    const float* w2_r = (const float*)d_in[8];
    const float* att2 = (const float*)d_in[9];
    const float* b2   = (const float*)d_in[10];
    const float* w3_l = (const float*)d_in[11];
    const float* w3_r = (const float*)d_in[12];
    const float* att3 = (const float*)d_in[13];
    const float* b3   = (const float*)d_in[14];
    const float* out_w = (const float*)d_in[15];
    const float* out_b = (const float*)d_in[16];
    float* out = (float*)d_out;

    void* p;
    float *xl, *xr, *h, *gsum; int *deg, *row, *fill, *col, *cnt; unsigned* gmax;
    cudaGetSymbolAddress(&p, g_xl);   xl   = (float*)p;
    cudaGetSymbolAddress(&p, g_xr);   xr   = (float*)p;
    cudaGetSymbolAddress(&p, g_h);    h    = (float*)p;
    cudaGetSymbolAddress(&p, g_deg);  deg  = (int*)p;
    cudaGetSymbolAddress(&p, g_row);  row  = (int*)p;
    cudaGetSymbolAddress(&p, g_fill); fill = (int*)p;
    cudaGetSymbolAddress(&p, g_col);  col  = (int*)p;
    cudaGetSymbolAddress(&p, g_gmax); gmax = (unsigned*)p;
    cudaGetSymbolAddress(&p, g_gsum); gsum = (float*)p;
    cudaGetSymbolAddress(&p, g_cnt);  cnt  = (int*)p;

    // --- CSR build ---
    init_kernel<<<(NN + 255) / 256, 256>>>(deg, gmax, gsum, cnt);
    hist_kernel<<<(ETOT + 255) / 256, 256>>>(edge_idx, deg);
    scan_kernel<<<1, 1024>>>(deg, row, fill);
    scatter_kernel<<<(ETOT + 255) / 256, 256>>>(edge_idx, fill, col);

    const int AGG_BLOCKS = (NN * 32) / 256;
    const int NB = (NN + 127) / 128;   // 391 row-blocks

    // --- Layer 1: 128 -> 4x64 = 256 ---
    tf32_gemm<<<dim3(4, NB), 256>>>(x, w1_l, xl, NN, 128, 256);
    tf32_gemm<<<dim3(4, NB), 256>>>(x, w1_r, xr, NN, 128, 256);
    gat_agg_kernel<4><<<AGG_BLOCKS, 256>>>(xl, xr, row, col, att1, b1, h);

    // --- Layer 2: 256 -> 2x64 = 128 ---
    tf32_gemm<<<dim3(2, NB), 256>>>(h, w2_l, xl, NN, 256, 128);
    tf32_gemm<<<dim3(2, NB), 256>>>(h, w2_r, xr, NN, 256, 128);
    gat_agg_kernel<2><<<AGG_BLOCKS, 256>>>(xl, xr, row, col, att2, b2, h);

    // --- Layer 3: 128 -> 1x64 = 64 ---
    tf32_gemm<<<dim3(1, NB), 256>>>(h, w3_l, xl, NN, 128, 64);
    tf32_gemm<<<dim3(1, NB), 256>>>(h, w3_r, xr, NN, 128, 64);
    gat_agg_kernel<1><<<AGG_BLOCKS, 256>>>(xl, xr, row, col, att3, b3, h);

    // --- Pooling + head ---
    pool_kernel<<<(NN * 64 + 255) / 256, 256>>>(h, batch, gmax, gsum, cnt);
    head_kernel<<<1, 256>>>(gmax, gsum, cnt, out_w, out_b, out);
}

// round 3
// speedup vs baseline: 2.2870x; 1.2934x over previous
#include <cuda_runtime.h>
#include <cuda_bf16.h>
#include <math.h>

// ---------------------------------------------------------------------------
// Problem constants
// ---------------------------------------------------------------------------
#define NN   50000
#define EE   400000
#define ETOT (EE + NN)
#define GG   256
#define FMAX 256

// ---------------------------------------------------------------------------
// Scratch
// ---------------------------------------------------------------------------
__device__ float g_xl[(size_t)NN * FMAX];
__device__ float g_xr[(size_t)NN * FMAX];
__device__ float g_h [(size_t)NN * FMAX];
__device__ int   g_deg [NN];
__device__ int   g_row [NN + 1];
__device__ int   g_fill[NN];
__device__ int   g_col [ETOT];

__device__ __forceinline__ float to_tf32(float x) {
    float r;
    asm("cvt.rna.tf32.f32 %0, %1;" : "=f"(r) : "f"(x));
    return r;
}

// ---------------------------------------------------------------------------
// Init: zero degree counters
// ---------------------------------------------------------------------------
__global__ void init_kernel(int* deg) {
    int i = blockIdx.x * blockDim.x + threadIdx.x;
    if (i < NN) deg[i] = 0;
}

// ---------------------------------------------------------------------------
// CSR build
// ---------------------------------------------------------------------------
__global__ void hist_kernel(const int* __restrict__ edge_index, int* deg) {
    int e = blockIdx.x * blockDim.x + threadIdx.x;
    if (e >= ETOT) return;
    int dst = (e < EE) ? edge_index[EE + e] : (e - EE);
    atomicAdd(&deg[dst], 1);
}

__global__ void scan_kernel(const int* __restrict__ deg, int* __restrict__ row,
                            int* __restrict__ fill) {
    __shared__ int wsum[32];
    __shared__ int carry_s;
    int tid = threadIdx.x, lane = tid & 31, wid = tid >> 5;
    if (tid == 0) carry_s = 0;
    __syncthreads();
    for (int base = 0; base < NN; base += 1024) {
        int i = base + tid;
        int v = (i < NN) ? deg[i] : 0;
        int x = v;
        #pragma unroll
        for (int o = 1; o < 32; o <<= 1) {
            int t = __shfl_up_sync(0xffffffffu, x, o);
            if (lane >= o) x += t;
        }
        if (lane == 31) wsum[wid] = x;
        __syncthreads();
        if (wid == 0) {
            int s = wsum[lane];
            #pragma unroll
            for (int o = 1; o < 32; o <<= 1) {
                int t = __shfl_up_sync(0xffffffffu, s, o);
                if (lane >= o) s += t;
            }
            wsum[lane] = s;
        }
        __syncthreads();
        int offset = carry_s + (wid > 0 ? wsum[wid - 1] : 0);
        int incl = offset + x;
        if (i < NN) { row[i + 1] = incl; fill[i] = incl - v; }
        if (i == 0) row[0] = 0;
        __syncthreads();
        if (tid == 1023) carry_s += wsum[31];
        __syncthreads();
    }
}

__global__ void scatter_kernel(const int* __restrict__ edge_index,
                               int* fill, int* __restrict__ col) {
    int e = blockIdx.x * blockDim.x + threadIdx.x;
    if (e >= ETOT) return;
    int src, dst;
    if (e < EE) { src = edge_index[e]; dst = edge_index[EE + e]; }
    else        { src = e - EE;        dst = e - EE; }
    int pos = atomicAdd(&fill[dst], 1);
    col[pos] = src;
}

// ---------------------------------------------------------------------------
// TF32 GEMM, fused l/r: z = blockIdx.z picks (W, C).
// C[N,M] = A[N,K] * W[M,K]^T. BM=128, BN=128, BK=32, 512 threads (16 warps 4x4).
// Warp tile 32x32 = 2(m16) x 4(n8). Smem rows padded to 36 floats.
// ---------------------------------------------------------------------------
__global__ __launch_bounds__(512) void tf32_gemm2(const float* __restrict__ A,
                                                  const float* __restrict__ Wl,
                                                  const float* __restrict__ Wr,
                                                  float* __restrict__ Cl,
                                                  float* __restrict__ Cr,
                                                  int Nrows, int K, int M) {
    __shared__ float As[128][36];
    __shared__ float Bs[128][36];

    const float* W = blockIdx.z ? Wr : Wl;
    float*       C = blockIdx.z ? Cr : Cl;

    int tid = threadIdx.x;
    int lane = tid & 31, wid = tid >> 5;
    int warpM = wid & 3, warpN = wid >> 2;
    int quad = lane >> 2, tq = lane & 3;
    int rowBase = blockIdx.y * 128;
    int colBase = blockIdx.x * 128;

    float acc[2][4][4];
    #pragma unroll
    for (int mi = 0; mi < 2; mi++)
        #pragma unroll
        for (int ni = 0; ni < 4; ni++)
            #pragma unroll
            for (int r = 0; r < 4; r++) acc[mi][ni][r] = 0.0f;

    for (int k0 = 0; k0 < K; k0 += 32) {
        float4 aReg[2], bReg[2];
        #pragma unroll
        for (int i = 0; i < 2; i++) {
            int fourIdx = tid + 512 * i;      // 0..1023
            int r = fourIdx >> 3;             // 0..127
            int kq = fourIdx & 7;
            int gr = rowBase + r;
            float4 v = make_float4(0.f, 0.f, 0.f, 0.f);
            if (gr < Nrows) v = *(const float4*)&A[(size_t)gr * K + k0 + kq * 4];
            aReg[i].x = to_tf32(v.x); aReg[i].y = to_tf32(v.y);
            aReg[i].z = to_tf32(v.z); aReg[i].w = to_tf32(v.w);

            int gbr = colBase + r;
            float4 w = make_float4(0.f, 0.f, 0.f, 0.f);
            if (gbr < M) w = *(const float4*)&W[(size_t)gbr * K + k0 + kq * 4];
            bReg[i].x = to_tf32(w.x); bReg[i].y = to_tf32(w.y);
            bReg[i].z = to_tf32(w.z); bReg[i].w = to_tf32(w.w);
        }

        __syncthreads();
        #pragma unroll
        for (int i = 0; i < 2; i++) {
            int fourIdx = tid + 512 * i;
            int r = fourIdx >> 3;
            int kq = fourIdx & 7;
            *(float4*)&As[r][kq * 4] = aReg[i];
            *(float4*)&Bs[r][kq * 4] = bReg[i];
        }
        __syncthreads();

        #pragma unroll
        for (int ks = 0; ks < 4; ks++) {
            int kk = ks * 8;
            unsigned a[2][4], b[4][2];
            #pragma unroll
            for (int mi = 0; mi < 2; mi++) {
                int r0 = warpM * 32 + mi * 16 + quad;
                a[mi][0] = __float_as_uint(As[r0    ][kk + tq]);
                a[mi][1] = __float_as_uint(As[r0 + 8][kk + tq]);
                a[mi][2] = __float_as_uint(As[r0    ][kk + tq + 4]);
                a[mi][3] = __float_as_uint(As[r0 + 8][kk + tq + 4]);
            }
            #pragma unroll
            for (int ni = 0; ni < 4; ni++) {
                int c0 = warpN * 32 + ni * 8 + quad;
                b[ni][0] = __float_as_uint(Bs[c0][kk + tq]);
                b[ni][1] = __float_as_uint(Bs[c0][kk + tq + 4]);
            }
            #pragma unroll
            for (int mi = 0; mi < 2; mi++)
                #pragma unroll
                for (int ni = 0; ni < 4; ni++) {
                    asm volatile(
                        "mma.sync.aligned.m16n8k8.row.col.f32.tf32.tf32.f32 "
                        "{%0,%1,%2,%3},{%4,%5,%6,%7},{%8,%9},{%0,%1,%2,%3};"
                        : "+f"(acc[mi][ni][0]), "+f"(acc[mi][ni][1]),
                          "+f"(acc[mi][ni][2]), "+f"(acc[mi][ni][3])
                        : "r"(a[mi][0]), "r"(a[mi][1]), "r"(a[mi][2]), "r"(a[mi][3]),
                          "r"(b[ni][0]), "r"(b[ni][1]));
                }
        }
        __syncthreads();
    }

    #pragma unroll
    for (int mi = 0; mi < 2; mi++) {
        #pragma unroll
        for (int half = 0; half < 2; half++) {
            int r = rowBase + warpM * 32 + mi * 16 + quad + half * 8;
            if (r >= Nrows) continue;
            #pragma unroll
            for (int ni = 0; ni < 4; ni++) {
                int c = colBase + warpN * 32 + ni * 8 + 2 * tq;
                if (c >= M) continue;
                float2 v;
                v.x = acc[mi][ni][half * 2 + 0];
                v.y = acc[mi][ni][half * 2 + 1];
                *(float2*)&C[(size_t)r * M + c] = v;
            }
        }
    }
}

// ---------------------------------------------------------------------------
// GATv2 aggregation, float4 layout. One warp per dst node, online softmax.
// H>=2: lane owns features f = 128*c + 4*lane + [0,4) for chunk c.
//       head(chunk c) = 2*c + (lane>>4); logits reduced over 16-lane groups.
// ---------------------------------------------------------------------------
__device__ __forceinline__ float4 lrelu4_02(float4 z) {
    z.x = z.x > 0.f ? z.x : 0.2f * z.x;
    z.y = z.y > 0.f ? z.y : 0.2f * z.y;
    z.z = z.z > 0.f ? z.z : 0.2f * z.z;
    z.w = z.w > 0.f ? z.w : 0.2f * z.w;
    return z;
}

template <int H>
__global__ __launch_bounds__(256) void gat_agg4_kernel(
    const float* __restrict__ xl, const float* __restrict__ xr,
    const int* __restrict__ rowptr, const int* __restrict__ colidx,
    const float* __restrict__ att, const float* __restrict__ bias,
    float* __restrict__ out) {
    constexpr int F = H * 64;
    constexpr int CH = F / 128;   // float4 chunks per lane (H=4 ->2, H=2 ->1)
    int warp = (blockIdx.x * blockDim.x + threadIdx.x) >> 5;
    int lane = threadIdx.x & 31;
    if (warp >= NN) return;

    const float4* xl4 = (const float4*)xl;
    const float4* xr4 = (const float4*)xr;
    const int rowF4 = F / 4;

    float4 xrr[CH], attr[CH];
    #pragma unroll
    for (int c = 0; c < CH; c++) {
        xrr[c]  = xr4[(size_t)warp * rowF4 + c * 32 + lane];
        attr[c] = ((const float4*)att)[c * 32 + lane];
    }

    float emax[CH], psum[CH];
    float4 acc[CH];
    #pragma unroll
    for (int c = 0; c < CH; c++) {
        emax[c] = -INFINITY; psum[c] = 0.0f;
        acc[c] = make_float4(0.f, 0.f, 0.f, 0.f);
    }

    int beg = rowptr[warp], end = rowptr[warp + 1];

    auto body = [&](const int s, float4* v) {
        float part[CH];
        #pragma unroll
        for (int c = 0; c < CH; c++) {
            float4 z = lrelu4_02(make_float4(v[c].x + xrr[c].x, v[c].y + xrr[c].y,
                                             v[c].z + xrr[c].z, v[c].w + xrr[c].w));
            part[c] = attr[c].x * z.x + attr[c].y * z.y +
                      attr[c].z * z.z + attr[c].w * z.w;
        }
        #pragma unroll
        for (int c = 0; c < CH; c++) {
            #pragma unroll
            for (int o = 1; o < 16; o <<= 1)
                part[c] += __shfl_xor_sync(0xffffffffu, part[c], o);
            part[c] += __shfl_xor_sync(0xffffffffu, part[c], 8); // no-op pattern avoided below
        }
        (void)s;
        return;
    };
    (void)body; // (lambda kept out of hot path; explicit code below)

    int j = beg;
    for (; j + 1 < end; j += 2) {
        int s0 = colidx[j], s1 = colidx[j + 1];
        float4 v0[CH], v1[CH];
        #pragma unroll
        for (int c = 0; c < CH; c++) {
            v0[c] = __ldg(&xl4[(size_t)s0 * rowF4 + c * 32 + lane]);
            v1[c] = __ldg(&xl4[(size_t)s1 * rowF4 + c * 32 + lane]);
        }
        float p0[CH], p1[CH];
        #pragma unroll
        for (int c = 0; c < CH; c++) {
            float4 z0 = lrelu4_02(make_float4(v0[c].x + xrr[c].x, v0[c].y + xrr[c].y,
                                              v0[c].z + xrr[c].z, v0[c].w + xrr[c].w));
            p0[c] = attr[c].x * z0.x + attr[c].y * z0.y + attr[c].z * z0.z + attr[c].w * z0.w;
            float4 z1 = lrelu4_02(make_float4(v1[c].x + xrr[c].x, v1[c].y + xrr[c].y,
                                              v1[c].z + xrr[c].z, v1[c].w + xrr[c].w));
            p1[c] = attr[c].x * z1.x + attr[c].y * z1.y + attr[c].z * z1.z + attr[c].w * z1.w;
        }
        #pragma unroll
        for (int c = 0; c < CH; c++) {
            #pragma unroll
            for (int o = 1; o < 16; o <<= 1) {
                p0[c] += __shfl_xor_sync(0xffffffffu, p0[c], o);
                p1[c] += __shfl_xor_sync(0xffffffffu, p1[c], o);
            }
        }
        #pragma unroll
        for (int c = 0; c < CH; c++) {
            // edge 0
            float m = fmaxf(emax[c], p0[c]);
            float cr = __expf(emax[c] - m);
            float pf = __expf(p0[c] - m);
            psum[c] = psum[c] * cr + pf;
            emax[c] = m;
            acc[c].x = acc[c].x * cr + pf * v0[c].x;
            acc[c].y = acc[c].y * cr + pf * v0[c].y;
            acc[c].z = acc[c].z * cr + pf * v0[c].z;
            acc[c].w = acc[c].w * cr + pf * v0[c].w;
            // edge 1
            m = fmaxf(emax[c], p1[c]);
            cr = __expf(emax[c] - m);
            pf = __expf(p1[c] - m);
            psum[c] = psum[c] * cr + pf;
            emax[c] = m;
            acc[c].x = acc[c].x * cr + pf * v1[c].x;
            acc[c].y = acc[c].y * cr + pf * v1[c].y;
            acc[c].z = acc[c].z * cr + pf * v1[c].z;
            acc[c].w = acc[c].w * cr + pf * v1[c].w;
        }
    }
    if (j < end) {
        int s0 = colidx[j];
        float4 v0[CH];
        #pragma unroll
        for (int c = 0; c < CH; c++)
            v0[c] = __ldg(&xl4[(size_t)s0 * rowF4 + c * 32 + lane]);
        float p0[CH];
        #pragma unroll
        for (int c = 0; c < CH; c++) {
            float4 z0 = lrelu4_02(make_float4(v0[c].x + xrr[c].x, v0[c].y + xrr[c].y,
                                              v0[c].z + xrr[c].z, v0[c].w + xrr[c].w));
            p0[c] = attr[c].x * z0.x + attr[c].y * z0.y + attr[c].z * z0.z + attr[c].w * z0.w;
            #pragma unroll
            for (int o = 1; o < 16; o <<= 1)
                p0[c] += __shfl_xor_sync(0xffffffffu, p0[c], o);
            float m = fmaxf(emax[c], p0[c]);
            float cr = __expf(emax[c] - m);
            float pf = __expf(p0[c] - m);
            psum[c] = psum[c] * cr + pf;
            emax[c] = m;
            acc[c].x = acc[c].x * cr + pf * v0[c].x;
            acc[c].y = acc[c].y * cr + pf * v0[c].y;
            acc[c].z = acc[c].z * cr + pf * v0[c].z;
            acc[c].w = acc[c].w * cr + pf * v0[c].w;
        }
    }

    #pragma unroll
    for (int c = 0; c < CH; c++) {
        float4 bi = ((const float4*)bias)[c * 32 + lane];
        float inv = 1.0f / (psum[c] + 1e-16f);
        float4 v;
        v.x = acc[c].x * inv + bi.x;
        v.y = acc[c].y * inv + bi.y;
        v.z = acc[c].z * inv + bi.z;
        v.w = acc[c].w * inv + bi.w;
        v.x = v.x > 0.f ? v.x : 0.01f * v.x;
        v.y = v.y > 0.f ? v.y : 0.01f * v.y;
        v.z = v.z > 0.f ? v.z : 0.01f * v.z;
        v.w = v.w > 0.f ? v.w : 0.01f * v.w;
        ((float4*)out)[(size_t)warp * rowF4 + c * 32 + lane] = v;
    }
}

// H = 1 specialization: F = 64, float2 per lane, reduce over full warp.
__global__ __launch_bounds__(256) void gat_agg1_kernel(
    const float* __restrict__ xl, const float* __restrict__ xr,
    const int* __restrict__ rowptr, const int* __restrict__ colidx,
    const float* __restrict__ att, const float* __restrict__ bias,
    float* __restrict__ out) {
    int warp = (blockIdx.x * blockDim.x + threadIdx.x) >> 5;
    int lane = threadIdx.x & 31;
    if (warp >= NN) return;

    const float2* xl2 = (const float2*)xl;
    float2 xrr = ((const float2*)xr)[(size_t)warp * 32 + lane];
    float2 attr = ((const float2*)att)[lane];

    float emax = -INFINITY, psum = 0.0f;
    float2 acc = make_float2(0.f, 0.f);

    int beg = rowptr[warp], end = rowptr[warp + 1];
    for (int j = beg; j < end; j++) {
        int s = colidx[j];
        float2 v = __ldg(&xl2[(size_t)s * 32 + lane]);
        float zx = v.x + xrr.x; zx = zx > 0.f ? zx : 0.2f * zx;
        float zy = v.y + xrr.y; zy = zy > 0.f ? zy : 0.2f * zy;
        float p = attr.x * zx + attr.y * zy;
        #pragma unroll
        for (int o = 16; o > 0; o >>= 1)
            p += __shfl_xor_sync(0xffffffffu, p, o);
        float m = fmaxf(emax, p);
        float cr = __expf(emax - m);
        float pf = __expf(p - m);
        psum = psum * cr + pf;
        emax = m;
        acc.x = acc.x * cr + pf * v.x;
        acc.y = acc.y * cr + pf * v.y;
    }

    float2 bi = ((const float2*)bias)[lane];
    float inv = 1.0f / (psum + 1e-16f);
    float2 v;
    v.x = acc.x * inv + bi.x;
    v.y = acc.y * inv + bi.y;
    v.x = v.x > 0.f ? v.x : 0.01f * v.x;
    v.y = v.y > 0.f ? v.y : 0.01f * v.y;
    ((float2*)out)[(size_t)warp * 32 + lane] = v;
}

// ---------------------------------------------------------------------------
// Fused pooling + head. batch_index is sorted -> one block per graph, node
// range found by binary search. No atomics.
// d_out: [0:512) out[256,2], [512:33280) hidden[256,128]
// ---------------------------------------------------------------------------
__global__ __launch_bounds__(256) void pool_head_kernel(
    const float* __restrict__ h, const int* __restrict__ batch,
    const float* __restrict__ out_w, const float* __restrict__ out_b,
    float* __restrict__ d_out) {
    int g = blockIdx.x;
    int t = threadIdx.x;
    int f = t & 63, slice = t >> 6;

    __shared__ int bounds[2];
    __shared__ float smax[4][64], ssum[4][64];
    __shared__ float hid[128];

    if (t < 2) {
        // lower_bound(batch, g + t)
        int key = g + t;
        int lo = 0, hi = NN;
        while (lo < hi) {
            int mid = (lo + hi) >> 1;
            if (batch[mid] < key) lo = mid + 1; else hi = mid;
        }
        bounds[t] = lo;
    }
    __syncthreads();
    int start = bounds[0], end = bounds[1];

    float mx = -INFINITY, sm = 0.0f;
    for (int n = start + slice; n < end; n += 4) {
        float v = h[(size_t)n * 64 + f];
        mx = fmaxf(mx, v);
        sm += v;
    }
    smax[slice][f] = mx;
    ssum[slice][f] = sm;
    __syncthreads();

    if (t < 64) {
        float m = fmaxf(fmaxf(smax[0][t], smax[1][t]), fmaxf(smax[2][t], smax[3][t]));
        float s = ssum[0][t] + ssum[1][t] + ssum[2][t] + ssum[3][t];
        int cnt = end - start;
        float inv = 1.0f / (float)(cnt > 1 ? cnt : 1);
        hid[t] = m;
        hid[64 + t] = s * inv;
    }
    __syncthreads();

    if (t < 128) d_out[512 + (size_t)g * 128 + t] = hid[t];
    if (t < 2) {
        float s = out_b[t];
        #pragma unroll 8
        for (int k = 0; k < 128; k++) s = fmaf(hid[k], out_w[t * 128 + k], s);
        d_out[g * 2 + t] = s;
    }
}

// ---------------------------------------------------------------------------
// Launch
// ---------------------------------------------------------------------------
extern "C" void kernel_launch(void* const* d_in, const int* in_sizes, int n_in,
                              void* d_out, int out_size) {
    const float* x        = (const float*)d_in[0];
    const int*   edge_idx = (const int*)d_in[1];
    const int*   batch    = (const int*)d_in[2];
    const float* w1_l = (const float*)d_in[3];
    const float* w1_r = (const float*)d_in[4];
    const float* att1 = (const float*)d_in[5];
    const float* b1   = (const float*)d_in[6];
    const float* w2_l = (const float*)d_in[7];
    const float* w2_r = (const float*)d_in[8];
    const float* att2 = (const float*)d_in[9];
    const float* b2   = (const float*)d_in[10];
    const float* w3_l = (const float*)d_in[11];
    const float* w3_r = (const float*)d_in[12];
    const float* att3 = (const float*)d_in[13];
    const float* b3   = (const float*)d_in[14];
    const float* out_w = (const float*)d_in[15];
    const float* out_b = (const float*)d_in[16];
    float* out = (float*)d_out;

    void* p;
    float *xl, *xr, *h; int *deg, *row, *fill, *col;
    cudaGetSymbolAddress(&p, g_xl);   xl   = (float*)p;
    cudaGetSymbolAddress(&p, g_xr);   xr   = (float*)p;
    cudaGetSymbolAddress(&p, g_h);    h    = (float*)p;
    cudaGetSymbolAddress(&p, g_deg);  deg  = (int*)p;
    cudaGetSymbolAddress(&p, g_row);  row  = (int*)p;
    cudaGetSymbolAddress(&p, g_fill); fill = (int*)p;
    cudaGetSymbolAddress(&p, g_col);  col  = (int*)p;

    // --- CSR build ---
    init_kernel<<<(NN + 255) / 256, 256>>>(deg);
    hist_kernel<<<(ETOT + 255) / 256, 256>>>(edge_idx, deg);
    scan_kernel<<<1, 1024>>>(deg, row, fill);
    scatter_kernel<<<(ETOT + 255) / 256, 256>>>(edge_idx, fill, col);

    const int AGG_BLOCKS = (NN * 32) / 256;
    const int NB = (NN + 127) / 128;

    // --- Layer 1: 128 -> 256 ---
    tf32_gemm2<<<dim3(2, NB, 2), 512>>>(x, w1_l, w1_r, xl, xr, NN, 128, 256);
    gat_agg4_kernel<4><<<AGG_BLOCKS, 256>>>(xl, xr, row, col, att1, b1, h);

    // --- Layer 2: 256 -> 128 ---
    tf32_gemm2<<<dim3(1, NB, 2), 512>>>(h, w2_l, w2_r, xl, xr, NN, 256, 128);
    gat_agg4_kernel<2><<<AGG_BLOCKS, 256>>>(xl, xr, row, col, att2, b2, h);

    // --- Layer 3: 128 -> 64 ---
    tf32_gemm2<<<dim3(1, NB, 2), 512>>>(h, w3_l, w3_r, xl, xr, NN, 128, 64);
    gat_agg1_kernel<<<AGG_BLOCKS, 256>>>(xl, xr, row, col, att3, b3, h);

    // --- Fused pooling + head ---
    pool_head_kernel<<<GG, 256>>>(h, batch, out_w, out_b, out);
}

// round 4
// speedup vs baseline: 2.5048x; 1.0952x over previous
#include <cuda_runtime.h>
#include <cuda_bf16.h>
#include <math.h>

// ---------------------------------------------------------------------------
// Problem constants
// ---------------------------------------------------------------------------
#define NN   50000
#define EE   400000
#define ETOT (EE + NN)
#define GG   256
#define FMAX 256
#define SCAN_BLK 1024
#define SCAN_NB  ((NN + SCAN_BLK - 1) / SCAN_BLK)   // 49

// ---------------------------------------------------------------------------
// Scratch
// ---------------------------------------------------------------------------
__device__ float g_xl[(size_t)NN * FMAX];
__device__ float g_xr[(size_t)NN * FMAX];
__device__ float g_h [(size_t)NN * FMAX];
__device__ int   g_deg [NN];
__device__ int   g_row [NN + 1];
__device__ int   g_fill[NN];
__device__ int   g_col [ETOT];
__device__ int   g_bsum[SCAN_NB];

__device__ __forceinline__ float to_tf32(float x) {
    float r;
    asm("cvt.rna.tf32.f32 %0, %1;" : "=f"(r) : "f"(x));
    return r;
}

// ---------------------------------------------------------------------------
// CSR build
// ---------------------------------------------------------------------------
__global__ void init_kernel(int* deg) {
    int i = blockIdx.x * blockDim.x + threadIdx.x;
    if (i < NN) deg[i] = 0;
}

__global__ void hist_kernel(const int* __restrict__ edge_index, int* deg) {
    int e = blockIdx.x * blockDim.x + threadIdx.x;
    if (e >= ETOT) return;
    int dst = (e < EE) ? edge_index[EE + e] : (e - EE);
    atomicAdd(&deg[dst], 1);
}

// Stage 1: per-block inclusive scan of deg -> row[i+1] (local), block total -> bsum
__global__ __launch_bounds__(SCAN_BLK) void scan_partial(
    const int* __restrict__ deg, int* __restrict__ row, int* __restrict__ bsum) {
    __shared__ int wsum[32];
    int tid = threadIdx.x, lane = tid & 31, wid = tid >> 5;
    int i = blockIdx.x * SCAN_BLK + tid;
    int v = (i < NN) ? deg[i] : 0;
    int x = v;
    #pragma unroll
    for (int o = 1; o < 32; o <<= 1) {
        int t = __shfl_up_sync(0xffffffffu, x, o);
        if (lane >= o) x += t;
    }
    if (lane == 31) wsum[wid] = x;
    __syncthreads();
    if (wid == 0) {
        int s = (lane < 32) ? wsum[lane] : 0;
        #pragma unroll
        for (int o = 1; o < 32; o <<= 1) {
            int t = __shfl_up_sync(0xffffffffu, s, o);
            if (lane >= o) s += t;
        }
        wsum[lane] = s;
    }
    __syncthreads();
    int incl = x + (wid > 0 ? wsum[wid - 1] : 0);
    if (i < NN) row[i + 1] = incl;
    if (tid == SCAN_BLK - 1) bsum[blockIdx.x] = incl;
}

// Stage 2: exclusive scan of the 49 block sums (single warp-ish block)
__global__ void scan_bsums(int* __restrict__ bsum) {
    __shared__ int s[SCAN_NB];
    int tid = threadIdx.x;
    if (tid < SCAN_NB) s[tid] = bsum[tid];
    __syncthreads();
    if (tid == 0) {
        int run = 0;
        #pragma unroll 1
        for (int b = 0; b < SCAN_NB; b++) { int t = s[b]; s[b] = run; run += t; }
    }
    __syncthreads();
    if (tid < SCAN_NB) bsum[tid] = s[tid];
}

// Stage 3: add block offsets, produce fill[] and row[0]
__global__ __launch_bounds__(SCAN_BLK) void scan_apply(
    const int* __restrict__ deg, int* __restrict__ row,
    int* __restrict__ fill, const int* __restrict__ bsum) {
    int i = blockIdx.x * SCAN_BLK + threadIdx.x;
    if (i >= NN) return;
    int incl = row[i + 1] + bsum[blockIdx.x];
    row[i + 1] = incl;
    fill[i] = incl - deg[i];
    if (i == 0) row[0] = 0;
}

__global__ void scatter_kernel(const int* __restrict__ edge_index,
                               int* fill, int* __restrict__ col) {
    int e = blockIdx.x * blockDim.x + threadIdx.x;
    if (e >= ETOT) return;
    int src, dst;
    if (e < EE) { src = edge_index[e]; dst = edge_index[EE + e]; }
    else        { src = e - EE;        dst = e - EE; }
    int pos = atomicAdd(&fill[dst], 1);
    col[pos] = src;
}

// ---------------------------------------------------------------------------
// TF32 GEMM, fused l/r (blockIdx.z). C[N,M] = A[N,K] * W[M,K]^T.
// BM=128, BN=128, BK=32, 512 threads.
// ---------------------------------------------------------------------------
__global__ __launch_bounds__(512) void tf32_gemm2(const float* __restrict__ A,
                                                  const float* __restrict__ Wl,
                                                  const float* __restrict__ Wr,
                                                  float* __restrict__ Cl,
                                                  float* __restrict__ Cr,
                                                  int Nrows, int K, int M) {
    __shared__ float As[128][36];
    __shared__ float Bs[128][36];

    const float* W = blockIdx.z ? Wr : Wl;
    float*       C = blockIdx.z ? Cr : Cl;

    int tid = threadIdx.x;
    int lane = tid & 31, wid = tid >> 5;
    int warpM = wid & 3, warpN = wid >> 2;
    int quad = lane >> 2, tq = lane & 3;
    int rowBase = blockIdx.y * 128;
    int colBase = blockIdx.x * 128;

    float acc[2][4][4];
    #pragma unroll
    for (int mi = 0; mi < 2; mi++)
        #pragma unroll
        for (int ni = 0; ni < 4; ni++)
            #pragma unroll
            for (int r = 0; r < 4; r++) acc[mi][ni][r] = 0.0f;

    for (int k0 = 0; k0 < K; k0 += 32) {
        float4 aReg[2], bReg[2];
        #pragma unroll
        for (int i = 0; i < 2; i++) {
            int fourIdx = tid + 512 * i;
            int r = fourIdx >> 3;
            int kq = fourIdx & 7;
            int gr = rowBase + r;
            float4 v = make_float4(0.f, 0.f, 0.f, 0.f);
            if (gr < Nrows) v = *(const float4*)&A[(size_t)gr * K + k0 + kq * 4];
            aReg[i].x = to_tf32(v.x); aReg[i].y = to_tf32(v.y);
            aReg[i].z = to_tf32(v.z); aReg[i].w = to_tf32(v.w);

            int gbr = colBase + r;
            float4 w = make_float4(0.f, 0.f, 0.f, 0.f);
            if (gbr < M) w = *(const float4*)&W[(size_t)gbr * K + k0 + kq * 4];
            bReg[i].x = to_tf32(w.x); bReg[i].y = to_tf32(w.y);
            bReg[i].z = to_tf32(w.z); bReg[i].w = to_tf32(w.w);
        }

        __syncthreads();
        #pragma unroll
        for (int i = 0; i < 2; i++) {
            int fourIdx = tid + 512 * i;
            int r = fourIdx >> 3;
            int kq = fourIdx & 7;
            *(float4*)&As[r][kq * 4] = aReg[i];
            *(float4*)&Bs[r][kq * 4] = bReg[i];
        }
        __syncthreads();

        #pragma unroll
        for (int ks = 0; ks < 4; ks++) {
            int kk = ks * 8;
            unsigned a[2][4], b[4][2];
            #pragma unroll
            for (int mi = 0; mi < 2; mi++) {
                int r0 = warpM * 32 + mi * 16 + quad;
                a[mi][0] = __float_as_uint(As[r0    ][kk + tq]);
                a[mi][1] = __float_as_uint(As[r0 + 8][kk + tq]);
                a[mi][2] = __float_as_uint(As[r0    ][kk + tq + 4]);
                a[mi][3] = __float_as_uint(As[r0 + 8][kk + tq + 4]);
            }
            #pragma unroll
            for (int ni = 0; ni < 4; ni++) {
                int c0 = warpN * 32 + ni * 8 + quad;
                b[ni][0] = __float_as_uint(Bs[c0][kk + tq]);
                b[ni][1] = __float_as_uint(Bs[c0][kk + tq + 4]);
            }
            #pragma unroll
            for (int mi = 0; mi < 2; mi++)
                #pragma unroll
                for (int ni = 0; ni < 4; ni++) {
                    asm volatile(
                        "mma.sync.aligned.m16n8k8.row.col.f32.tf32.tf32.f32 "
                        "{%0,%1,%2,%3},{%4,%5,%6,%7},{%8,%9},{%0,%1,%2,%3};"
                        : "+f"(acc[mi][ni][0]), "+f"(acc[mi][ni][1]),
                          "+f"(acc[mi][ni][2]), "+f"(acc[mi][ni][3])
                        : "r"(a[mi][0]), "r"(a[mi][1]), "r"(a[mi][2]), "r"(a[mi][3]),
                          "r"(b[ni][0]), "r"(b[ni][1]));
                }
        }
        __syncthreads();
    }

    #pragma unroll
    for (int mi = 0; mi < 2; mi++) {
        #pragma unroll
        for (int half = 0; half < 2; half++) {
            int r = rowBase + warpM * 32 + mi * 16 + quad + half * 8;
            if (r >= Nrows) continue;
            #pragma unroll
            for (int ni = 0; ni < 4; ni++) {
                int c = colBase + warpN * 32 + ni * 8 + 2 * tq;
                if (c >= M) continue;
                float2 v;
                v.x = acc[mi][ni][half * 2 + 0];
                v.y = acc[mi][ni][half * 2 + 1];
                *(float2*)&C[(size_t)r * M + c] = v;
            }
        }
    }
}

// ---------------------------------------------------------------------------
// GATv2 aggregation, warp per (node, 128-feature chunk), 4-edge unroll.
// Lane owns features f = 128*chunk + 4*lane + [0,4). head = 2*chunk + (lane>>4)
// -> logits reduced over 16-lane groups (XOR 1,2,4,8 keeps bit4).
// ---------------------------------------------------------------------------
__device__ __forceinline__ float dot_lrelu(float4 v, float4 xrr, float4 attr) {
    float zx = v.x + xrr.x; zx = zx > 0.f ? zx : 0.2f * zx;
    float zy = v.y + xrr.y; zy = zy > 0.f ? zy : 0.2f * zy;
    float zz = v.z + xrr.z; zz = zz > 0.f ? zz : 0.2f * zz;
    float zw = v.w + xrr.w; zw = zw > 0.f ? zw : 0.2f * zw;
    return attr.x * zx + attr.y * zy + attr.z * zz + attr.w * zw;
}
__device__ __forceinline__ void osm_update(float p, const float4& v,
                                           float& emax, float& psum, float4& acc) {
    float m = fmaxf(emax, p);
    float cr = __expf(emax - m);
    float pf = __expf(p - m);
    psum = psum * cr + pf;
    emax = m;
    acc.x = acc.x * cr + pf * v.x;
    acc.y = acc.y * cr + pf * v.y;
    acc.z = acc.z * cr + pf * v.z;
    acc.w = acc.w * cr + pf * v.w;
}

// F: full feature width (256 or 128). chunk = blockIdx.y.
template <int F>
__global__ __launch_bounds__(256) void gat_agg_chunk_kernel(
    const float* __restrict__ xl, const float* __restrict__ xr,
    const int* __restrict__ rowptr, const int* __restrict__ colidx,
    const float* __restrict__ att, const float* __restrict__ bias,
    float* __restrict__ out) {
    constexpr int rowF4 = F / 4;
    int node = (blockIdx.x * blockDim.x + threadIdx.x) >> 5;
    int lane = threadIdx.x & 31;
    if (node >= NN) return;
    int chunk = blockIdx.y;
    int fi = chunk * 32 + lane;   // float4 index within row

    const float4* xl4 = (const float4*)xl;
    float4 xrr  = ((const float4*)xr)[(size_t)node * rowF4 + fi];
    float4 attr = ((const float4*)att)[fi];

    float emax = -INFINITY, psum = 0.0f;
    float4 acc = make_float4(0.f, 0.f, 0.f, 0.f);

    int beg = rowptr[node], end = rowptr[node + 1];
    int j = beg;
    for (; j + 4 <= end; j += 4) {
        int s0 = colidx[j], s1 = colidx[j + 1], s2 = colidx[j + 2], s3 = colidx[j + 3];
        float4 v0 = __ldg(&xl4[(size_t)s0 * rowF4 + fi]);
        float4 v1 = __ldg(&xl4[(size_t)s1 * rowF4 + fi]);
        float4 v2 = __ldg(&xl4[(size_t)s2 * rowF4 + fi]);
        float4 v3 = __ldg(&xl4[(size_t)s3 * rowF4 + fi]);
        float p0 = dot_lrelu(v0, xrr, attr);
        float p1 = dot_lrelu(v1, xrr, attr);
        float p2 = dot_lrelu(v2, xrr, attr);
        float p3 = dot_lrelu(v3, xrr, attr);
        #pragma unroll
        for (int o = 1; o < 16; o <<= 1) {
            p0 += __shfl_xor_sync(0xffffffffu, p0, o);
            p1 += __shfl_xor_sync(0xffffffffu, p1, o);
            p2 += __shfl_xor_sync(0xffffffffu, p2, o);
            p3 += __shfl_xor_sync(0xffffffffu, p3, o);
        }
        osm_update(p0, v0, emax, psum, acc);
        osm_update(p1, v1, emax, psum, acc);
        osm_update(p2, v2, emax, psum, acc);
        osm_update(p3, v3, emax, psum, acc);
    }
    for (; j < end; j++) {
        int s0 = colidx[j];
        float4 v0 = __ldg(&xl4[(size_t)s0 * rowF4 + fi]);
        float p0 = dot_lrelu(v0, xrr, attr);
        #pragma unroll
        for (int o = 1; o < 16; o <<= 1)
            p0 += __shfl_xor_sync(0xffffffffu, p0, o);
        osm_update(p0, v0, emax, psum, acc);
    }

    float4 bi = ((const float4*)bias)[fi];
    float inv = 1.0f / (psum + 1e-16f);
    float4 v;
    v.x = acc.x * inv + bi.x;
    v.y = acc.y * inv + bi.y;
    v.z = acc.z * inv + bi.z;
    v.w = acc.w * inv + bi.w;
    v.x = v.x > 0.f ? v.x : 0.01f * v.x;
    v.y = v.y > 0.f ? v.y : 0.01f * v.y;
    v.z = v.z > 0.f ? v.z : 0.01f * v.z;
    v.w = v.w > 0.f ? v.w : 0.01f * v.w;
    ((float4*)out)[(size_t)node * rowF4 + fi] = v;
}

// H = 1 (F = 64): float2 per lane, full-warp reduce, 4-edge unroll.
__global__ __launch_bounds__(256) void gat_agg1_kernel(
    const float* __restrict__ xl, const float* __restrict__ xr,
    const int* __restrict__ rowptr, const int* __restrict__ colidx,
    const float* __restrict__ att, const float* __restrict__ bias,
    float* __restrict__ out) {
    int node = (blockIdx.x * blockDim.x + threadIdx.x) >> 5;
    int lane = threadIdx.x & 31;
    if (node >= NN) return;

    const float2* xl2 = (const float2*)xl;
    float2 xrr = ((const float2*)xr)[(size_t)node * 32 + lane];
    float2 attr = ((const float2*)att)[lane];

    float emax = -INFINITY, psum = 0.0f;
    float2 acc = make_float2(0.f, 0.f);

    auto dot2 = [&](float2 v) {
        float zx = v.x + xrr.x; zx = zx > 0.f ? zx : 0.2f * zx;
        float zy = v.y + xrr.y; zy = zy > 0.f ? zy : 0.2f * zy;
        return attr.x * zx + attr.y * zy;
    };
    auto upd2 = [&](float p, float2 v) {
        float m = fmaxf(emax, p);
        float cr = __expf(emax - m);
        float pf = __expf(p - m);
        psum = psum * cr + pf;
        emax = m;
        acc.x = acc.x * cr + pf * v.x;
        acc.y = acc.y * cr + pf * v.y;
    };

    int beg = rowptr[node], end = rowptr[node + 1];
    int j = beg;
    for (; j + 4 <= end; j += 4) {
        int s0 = colidx[j], s1 = colidx[j + 1], s2 = colidx[j + 2], s3 = colidx[j + 3];
        float2 v0 = __ldg(&xl2[(size_t)s0 * 32 + lane]);
        float2 v1 = __ldg(&xl2[(size_t)s1 * 32 + lane]);
        float2 v2 = __ldg(&xl2[(size_t)s2 * 32 + lane]);
        float2 v3 = __ldg(&xl2[(size_t)s3 * 32 + lane]);
        float p0 = dot2(v0), p1 = dot2(v1), p2 = dot2(v2), p3 = dot2(v3);
        #pragma unroll
        for (int o = 1; o < 32; o <<= 1) {
            p0 += __shfl_xor_sync(0xffffffffu, p0, o);
            p1 += __shfl_xor_sync(0xffffffffu, p1, o);
            p2 += __shfl_xor_sync(0xffffffffu, p2, o);
            p3 += __shfl_xor_sync(0xffffffffu, p3, o);
        }
        upd2(p0, v0); upd2(p1, v1); upd2(p2, v2); upd2(p3, v3);
    }
    for (; j < end; j++) {
        int s0 = colidx[j];
        float2 v0 = __ldg(&xl2[(size_t)s0 * 32 + lane]);
        float p0 = dot2(v0);
        #pragma unroll
        for (int o = 1; o < 32; o <<= 1)
            p0 += __shfl_xor_sync(0xffffffffu, p0, o);
        upd2(p0, v0);
    }

    float2 bi = ((const float2*)bias)[lane];
    float inv = 1.0f / (psum + 1e-16f);
    float2 v;
    v.x = acc.x * inv + bi.x;
    v.y = acc.y * inv + bi.y;
    v.x = v.x > 0.f ? v.x : 0.01f * v.x;
    v.y = v.y > 0.f ? v.y : 0.01f * v.y;
    ((float2*)out)[(size_t)node * 32 + lane] = v;
}

// ---------------------------------------------------------------------------
// Fused pooling + head (batch_index sorted -> binary-searched ranges)
// ---------------------------------------------------------------------------
__global__ __launch_bounds__(256) void pool_head_kernel(
    const float* __restrict__ h, const int* __restrict__ batch,
    const float* __restrict__ out_w, const float* __restrict__ out_b,
    float* __restrict__ d_out) {
    int g = blockIdx.x;
    int t = threadIdx.x;
    int f = t & 63, slice = t >> 6;

    __shared__ int bounds[2];
    __shared__ float smax[4][64], ssum[4][64];
    __shared__ float hid[128];

    if (t < 2) {
        int key = g + t;
        int lo = 0, hi = NN;
        while (lo < hi) {
            int mid = (lo + hi) >> 1;
            if (batch[mid] < key) lo = mid + 1; else hi = mid;
        }
        bounds[t] = lo;
    }
    __syncthreads();
    int start = bounds[0], end = bounds[1];

    float mx = -INFINITY, sm = 0.0f;
    for (int n = start + slice; n < end; n += 4) {
        float v = h[(size_t)n * 64 + f];
        mx = fmaxf(mx, v);
        sm += v;
    }
    smax[slice][f] = mx;
    ssum[slice][f] = sm;
    __syncthreads();

    if (t < 64) {
        float m = fmaxf(fmaxf(smax[0][t], smax[1][t]), fmaxf(smax[2][t], smax[3][t]));
        float s = ssum[0][t] + ssum[1][t] + ssum[2][t] + ssum[3][t];
        int cnt = end - start;
        float inv = 1.0f / (float)(cnt > 1 ? cnt : 1);
        hid[t] = m;
        hid[64 + t] = s * inv;
    }
    __syncthreads();

    if (t < 128) d_out[512 + (size_t)g * 128 + t] = hid[t];
    if (t < 2) {
        float s = out_b[t];
        #pragma unroll 8
        for (int k = 0; k < 128; k++) s = fmaf(hid[k], out_w[t * 128 + k], s);
        d_out[g * 2 + t] = s;
    }
}

// ---------------------------------------------------------------------------
// Launch
// ---------------------------------------------------------------------------
extern "C" void kernel_launch(void* const* d_in, const int* in_sizes, int n_in,
                              void* d_out, int out_size) {
    const float* x        = (const float*)d_in[0];
    const int*   edge_idx = (const int*)d_in[1];
    const int*   batch    = (const int*)d_in[2];
    const float* w1_l = (const float*)d_in[3];
    const float* w1_r = (const float*)d_in[4];
    const float* att1 = (const float*)d_in[5];
    const float* b1   = (const float*)d_in[6];
    const float* w2_l = (const float*)d_in[7];
    const float* w2_r = (const float*)d_in[8];
    const float* att2 = (const float*)d_in[9];
    const float* b2   = (const float*)d_in[10];
    const float* w3_l = (const float*)d_in[11];
    const float* w3_r = (const float*)d_in[12];
    const float* att3 = (const float*)d_in[13];
    const float* b3   = (const float*)d_in[14];
    const float* out_w = (const float*)d_in[15];
    const float* out_b = (const float*)d_in[16];
    float* out = (float*)d_out;

    void* p;
    float *xl, *xr, *h; int *deg, *row, *fill, *col, *bsum;
    cudaGetSymbolAddress(&p, g_xl);   xl   = (float*)p;
    cudaGetSymbolAddress(&p, g_xr);   xr   = (float*)p;
    cudaGetSymbolAddress(&p, g_h);    h    = (float*)p;
    cudaGetSymbolAddress(&p, g_deg);  deg  = (int*)p;
    cudaGetSymbolAddress(&p, g_row);  row  = (int*)p;
    cudaGetSymbolAddress(&p, g_fill); fill = (int*)p;
    cudaGetSymbolAddress(&p, g_col);  col  = (int*)p;
    cudaGetSymbolAddress(&p, g_bsum); bsum = (int*)p;

    // --- CSR build ---
    init_kernel<<<(NN + 255) / 256, 256>>>(deg);
    hist_kernel<<<(ETOT + 255) / 256, 256>>>(edge_idx, deg);
    scan_partial<<<SCAN_NB, SCAN_BLK>>>(deg, row, bsum);
    scan_bsums<<<1, 64>>>(bsum);
    scan_apply<<<SCAN_NB, SCAN_BLK>>>(deg, row, fill, bsum);
    scatter_kernel<<<(ETOT + 255) / 256, 256>>>(edge_idx, fill, col);

    const int AGG_BLOCKS = (NN * 32 + 255) / 256;
    const int NB = (NN + 127) / 128;

    // --- Layer 1: 128 -> 256 (H=4 -> 2 chunks of 128 features) ---
    tf32_gemm2<<<dim3(2, NB, 2), 512>>>(x, w1_l, w1_r, xl, xr, NN, 128, 256);
    gat_agg_chunk_kernel<256><<<dim3(AGG_BLOCKS, 2), 256>>>(xl, xr, row, col, att1, b1, h);

    // --- Layer 2: 256 -> 128 (H=2 -> 1 chunk) ---
    tf32_gemm2<<<dim3(1, NB, 2), 512>>>(h, w2_l, w2_r, xl, xr, NN, 256, 128);
    gat_agg_chunk_kernel<128><<<dim3(AGG_BLOCKS, 1), 256>>>(xl, xr, row, col, att2, b2, h);

    // --- Layer 3: 128 -> 64 (H=1) ---
    tf32_gemm2<<<dim3(1, NB, 2), 512>>>(h, w3_l, w3_r, xl, xr, NN, 128, 64);
    gat_agg1_kernel<<<AGG_BLOCKS, 256>>>(xl, xr, row, col, att3, b3, h);

    // --- Fused pooling + head ---
    pool_head_kernel<<<GG, 256>>>(h, batch, out_w, out_b, out);
}